// round 12
// baseline (speedup 1.0000x reference)
#include <cuda_runtime.h>
#include <math.h>
#include <stdint.h>

#define BATCH 128
#define SEQ   512
#define DIM   768
#define NCLS  9
#define NCHUNK 64             // 8 steps per chunk (CRF), covers t=1..512
#define TILE_ROWS 16
#define TILE_BYTES (TILE_ROWS * DIM * 4)   // 49152
#define NSTAGE 3
#define NTILE (SEQ / TILE_ROWS)            // 32

// dynamic smem layout (bytes)
#define OFF_W     0                        // 27648  W as 16B packs
#define OFF_BIAS  27648                    // 64
#define OFF_PART  27712                    // 4608   partials [8][16][9]
#define OFF_MBAR  32320                    // 64     3 mbarriers
#define OFF_FBUF  32384                    // 3 * 49152
#define SMEM_TOTAL (OFF_FBUF + NSTAGE * TILE_BYTES)   // 179840

// CRF-phase aliases (over the feature buffers, after gemm done)
#define OFF_EE   32384     // 18432
#define OFF_B8   50816     // 20736
#define OFF_TRT  71552     // 432
#define OFF_TRS  71984     // 324 (pad)
#define OFF_TAG  72320     // 2048
#define OFF_MSK  74368     // 2052 (pad)
#define OFF_ST   76432     // 36 (pad)
#define OFF_EN   76480     // 36

__device__ float g_llh[BATCH];
__device__ int   g_done;      // zero-init; self-resets each run (graph-replay safe)

// ---------------------------------------------------------------------------
// helpers
// ---------------------------------------------------------------------------
__device__ __forceinline__ uint32_t smem_u32(const void* p) {
    uint32_t a;
    asm("{ .reg .u64 t; cvta.to.shared.u64 t, %1; cvt.u32.u64 %0, t; }"
        : "=r"(a) : "l"(p));
    return a;
}

__device__ __forceinline__ unsigned long long ffma2(
    unsigned long long a, unsigned long long b, unsigned long long c)
{
    unsigned long long d;
    asm("fma.rn.f32x2 %0, %1, %2, %3;" : "=l"(d) : "l"(a), "l"(b), "l"(c));
    return d;
}

__device__ __forceinline__ float unpack_sum(unsigned long long v)
{
    float2 f = *reinterpret_cast<float2*>(&v);
    return f.x + f.y;
}

__device__ __forceinline__ void mbar_init(uint32_t addr, uint32_t count) {
    asm volatile("mbarrier.init.shared.b64 [%0], %1;" :: "r"(addr), "r"(count) : "memory");
}
__device__ __forceinline__ void mbar_expect_tx(uint32_t addr, uint32_t bytes) {
    asm volatile("mbarrier.arrive.expect_tx.shared.b64 _, [%0], %1;"
                 :: "r"(addr), "r"(bytes) : "memory");
}
__device__ __forceinline__ void mbar_wait(uint32_t addr, uint32_t parity) {
    asm volatile(
        "{\n\t.reg .pred P;\n\t"
        "WAITLP_%=:\n\t"
        "mbarrier.try_wait.parity.acquire.cta.shared::cta.b64 P, [%0], %1, 0x989680;\n\t"
        "@P bra.uni WDONE_%=;\n\t"
        "bra.uni WAITLP_%=;\n\t"
        "WDONE_%=:\n\t}"
        :: "r"(addr), "r"(parity) : "memory");
}
__device__ __forceinline__ void bulk_g2s(uint32_t dst, const void* src,
                                         uint32_t bytes, uint32_t mbar) {
    asm volatile(
        "cp.async.bulk.shared::cta.global.mbarrier::complete_tx::bytes [%0], [%1], %2, [%3];"
        :: "r"(dst), "l"(src), "r"(bytes), "r"(mbar) : "memory");
}
__device__ __forceinline__ void fence_proxy_async_s() {
    asm volatile("fence.proxy.async.shared::cta;" ::: "memory");
}

// ---------------------------------------------------------------------------
// Fused kernel: one block per batch element.
//  Phase G: GEMM of this batch's 512 rows, features streamed via 3-stage
//           cp.async.bulk pipeline (copy engine saturates HBM; warps compute
//           from smem). Warp = 8 rows x 1/8 of D; FFMA2 accumulation;
//           8-way partial reduce in smem; logits -> gmem.
//  Phase A-D: CRF NLL (R11 structure), smem re-aliased over feat buffers.
// ---------------------------------------------------------------------------
__global__ __launch_bounds__(512, 1) void fused_kernel(
    const float* __restrict__ feat,
    const int*   __restrict__ labels,
    const int*   __restrict__ mask,
    const float* __restrict__ W,
    const float* __restrict__ bias,
    const float* __restrict__ start_t,
    const float* __restrict__ end_t,
    const float* __restrict__ trans,
    float*       __restrict__ out)
{
    extern __shared__ char smem[];
    __shared__ float num_sh, den_sh;
    __shared__ int   isLast;
    __shared__ float wsum[4];

    const int b    = blockIdx.x;
    const int tid  = threadIdx.x;
    const int warp = tid >> 5;
    const int lane = tid & 31;
    const int li   = lane & 7;    // d-chunk lane within group
    const int g    = lane >> 3;   // group 0..3

    ulonglong2* Ws   = (ulonglong2*)(smem + OFF_W);
    float*      bS   = (float*)(smem + OFF_BIAS);
    float*      part = (float*)(smem + OFF_PART);
    const uint32_t mb0 = smem_u32(smem + OFF_MBAR);

    // ---- Phase G prologue ----
    const ulonglong2* Wg = (const ulonglong2*)W;
    for (int i = tid; i < NCLS * DIM / 4; i += 512) Ws[i] = Wg[i];   // 1728 packs
    if (tid < NCLS) bS[tid] = bias[tid];
    if (tid == 0) {
        for (int s = 0; s < NSTAGE; ++s) mbar_init(mb0 + 8 * s, 1);
        fence_proxy_async_s();
    }
    __syncthreads();

    const float* featb = feat + (size_t)b * SEQ * DIM;
    float*       lgb   = out + 1 + (size_t)b * SEQ * NCLS;

    if (tid == 0) {
#pragma unroll
        for (int s = 0; s < NSTAGE; ++s) {
            mbar_expect_tx(mb0 + 8 * s, TILE_BYTES);
            bulk_g2s(smem_u32(smem + OFF_FBUF + s * TILE_BYTES),
                     featb + s * (TILE_BYTES / 4), TILE_BYTES, mb0 + 8 * s);
        }
    }

    const int qa  = warp >> 1;          // d-eighth: 0..7 (3 chunks of 8 float4)
    const int rw  = warp & 1;           // row-octet within 16-row tile
    const int lr0 = rw * 8 + g * 2;     // local rows lr0, lr0+1
    const int lr1 = lr0 + 1;

    for (int t = 0; t < NTILE; ++t) {
        const int s = t % 3;
        mbar_wait(mb0 + 8 * s, (t / 3) & 1);

        const char* buf = smem + OFF_FBUF + s * TILE_BYTES;
        const ulonglong2* fa = (const ulonglong2*)(buf + lr0 * 3072);
        const ulonglong2* fb = (const ulonglong2*)(buf + lr1 * 3072);

        unsigned long long accA[NCLS], accB[NCLS];
#pragma unroll
        for (int n = 0; n < NCLS; ++n) { accA[n] = 0ull; accB[n] = 0ull; }

#pragma unroll
        for (int k = 0; k < 3; ++k) {
            const int idx = (qa * 3 + k) * 8 + li;   // 0..191
            const ulonglong2 a  = fa[idx];
            const ulonglong2 bv = fb[idx];
#pragma unroll
            for (int n = 0; n < NCLS; ++n) {
                const ulonglong2 w = Ws[n * 192 + idx];
                accA[n] = ffma2(a.x,  w.x, accA[n]);
                accA[n] = ffma2(a.y,  w.y, accA[n]);
                accB[n] = ffma2(bv.x, w.x, accB[n]);
                accB[n] = ffma2(bv.y, w.y, accB[n]);
            }
        }

        float ra[NCLS], rb[NCLS];
#pragma unroll
        for (int n = 0; n < NCLS; ++n) {
            ra[n] = unpack_sum(accA[n]);
            rb[n] = unpack_sum(accB[n]);
#pragma unroll
            for (int off = 4; off; off >>= 1) {
                ra[n] += __shfl_down_sync(0xffffffffu, ra[n], off, 8);
                rb[n] += __shfl_down_sync(0xffffffffu, rb[n], off, 8);
            }
        }
        if (li == 0) {
            float* pq = part + qa * (TILE_ROWS * NCLS);
#pragma unroll
            for (int n = 0; n < NCLS; ++n) {
                pq[lr0 * NCLS + n] = ra[n];
                pq[lr1 * NCLS + n] = rb[n];
            }
        }
        __syncthreads();

        if (tid < TILE_ROWS * NCLS) {   // 144 outputs
            const int row = tid / NCLS;
            const int n   = tid - row * NCLS;
            float v = bS[n];
#pragma unroll
            for (int q = 0; q < 8; ++q)
                v += part[q * (TILE_ROWS * NCLS) + row * NCLS + n];
            lgb[(t * TILE_ROWS + row) * NCLS + n] = v;
        }
        __syncthreads();

        if (tid == 0 && t + NSTAGE < NTILE) {
            mbar_expect_tx(mb0 + 8 * s, TILE_BYTES);
            bulk_g2s(smem_u32(smem + OFF_FBUF + s * TILE_BYTES),
                     featb + (size_t)(t + NSTAGE) * TILE_ROWS * DIM,
                     TILE_BYTES, mb0 + 8 * s);
        }
    }
    __syncthreads();

    // =======================  CRF phase  =======================
    float* EE   = (float*)(smem + OFF_EE);
    float* B8   = (float*)(smem + OFF_B8);
    float* trT  = (float*)(smem + OFF_TRT);
    float* trS  = (float*)(smem + OFF_TRS);
    int*   tagS = (int*)(smem + OFF_TAG);
    int*   mS   = (int*)(smem + OFF_MSK);
    float* stS  = (float*)(smem + OFF_ST);
    float* enS  = (float*)(smem + OFF_EN);

    // ---- Phase A: staging ----
    for (int i = tid; i < SEQ * NCLS; i += 512)
        EE[i] = __expf(lgb[i]);
    for (int i = tid; i < SEQ; i += 512) {
        const int lab = labels[(size_t)b * SEQ + i];
        tagS[i] = (lab == -100) ? 0 : lab;
        mS[i]   = (mask[(size_t)b * SEQ + i] != 0) ? 1 : 0;
    }
    if (tid == 0) mS[SEQ] = 0;
    if (tid < NCLS * NCLS) {
        const float tv = trans[tid];
        trS[tid] = tv;
        const int i = tid / NCLS, k = tid % NCLS;
        trT[k * 12 + i] = __expf(tv);
    }
    if (tid < NCLS) { stS[tid] = start_t[tid]; enS[tid] = end_t[tid]; }
    __syncthreads();

    // ---- Phase B: build B8 (576 column tasks over 512 threads) ----
    for (int task = tid; task < NCHUNK * NCLS; task += 512) {
        const int c = task / NCLS;
        const int j = task - c * NCLS;
        float v[NCLS];
#pragma unroll
        for (int i = 0; i < NCLS; ++i) v[i] = (i == j) ? 1.f : 0.f;

#pragma unroll
        for (int s = 7; s >= 0; --s) {
            const int t = 8 * c + 1 + s;
            if (mS[t]) {
                const float* eT = &EE[t * NCLS];
                float4 va = make_float4(0.f, 0.f, 0.f, 0.f);
                float4 vb = make_float4(0.f, 0.f, 0.f, 0.f);
                float  v8 = 0.f;
#pragma unroll
                for (int k = 0; k < NCLS; ++k) {
                    const float u = eT[k] * v[k];
                    const float4 t0 = *reinterpret_cast<const float4*>(trT + k * 12 + 0);
                    const float4 t1 = *reinterpret_cast<const float4*>(trT + k * 12 + 4);
                    const float  t2 = trT[k * 12 + 8];
                    va.x = fmaf(t0.x, u, va.x); va.y = fmaf(t0.y, u, va.y);
                    va.z = fmaf(t0.z, u, va.z); va.w = fmaf(t0.w, u, va.w);
                    vb.x = fmaf(t1.x, u, vb.x); vb.y = fmaf(t1.y, u, vb.y);
                    vb.z = fmaf(t1.z, u, vb.z); vb.w = fmaf(t1.w, u, vb.w);
                    v8   = fmaf(t2,   u, v8);
                }
                v[0] = va.x; v[1] = va.y; v[2] = va.z; v[3] = va.w;
                v[4] = vb.x; v[5] = vb.y; v[6] = vb.z; v[7] = vb.w;
                v[8] = v8;
            }
        }
#pragma unroll
        for (int i = 0; i < NCLS; ++i)
            B8[c * 81 + i * NCLS + j] = v[i];
    }
    __syncthreads();

    // ---- Phase C ----
    if (warp == 0) {
        const int j = (lane < NCLS) ? lane : 0;
        float p = (lane < NCLS) ? __expf(stS[j] + lgb[j]) : 0.f;
        float clog = 0.f;

        float bcol[NCLS];
#pragma unroll
        for (int i = 0; i < NCLS; ++i) bcol[i] = B8[i * NCLS + j];

        for (int ch = 0; ch < NCHUNK; ++ch) {
            float nb[NCLS];
            if (ch < NCHUNK - 1) {
                const float* base = B8 + (ch + 1) * 81 + j;
#pragma unroll
                for (int i = 0; i < NCLS; ++i) nb[i] = base[i * NCLS];
            }

            const float p0 = __shfl_sync(0xffffffffu, p, 0);
            const float p1 = __shfl_sync(0xffffffffu, p, 1);
            const float p2 = __shfl_sync(0xffffffffu, p, 2);
            const float p3 = __shfl_sync(0xffffffffu, p, 3);
            const float p4 = __shfl_sync(0xffffffffu, p, 4);
            const float p5 = __shfl_sync(0xffffffffu, p, 5);
            const float p6 = __shfl_sync(0xffffffffu, p, 6);
            const float p7 = __shfl_sync(0xffffffffu, p, 7);
            const float p8 = __shfl_sync(0xffffffffu, p, 8);

            const float s0 = fmaf(p2, bcol[2], fmaf(p1, bcol[1], p0 * bcol[0]));
            const float s1 = fmaf(p5, bcol[5], fmaf(p4, bcol[4], p3 * bcol[3]));
            const float s2 = fmaf(p8, bcol[8], fmaf(p7, bcol[7], p6 * bcol[6]));
            float pn = (s0 + s1) + s2;

            if (ch & 1) {
                const float sv = __shfl_sync(0xffffffffu, pn, 0);
                pn *= __frcp_rn(sv);
                clog += __logf(sv);
            }
            p = pn;
#pragma unroll
            for (int i = 0; i < NCLS; ++i) bcol[i] = nb[i];
        }

        float v = (lane < NCLS) ? p * __expf(enS[j]) : 0.f;
#pragma unroll
        for (int off = 16; off; off >>= 1)
            v += __shfl_xor_sync(0xffffffffu, v, off);
        if (lane == 0) den_sh = clog + __logf(v);
    }
    else if (warp == 1) {
        float sc = 0.f;
        int   cnt = 0;
        for (int t = lane; t < SEQ; t += 32) {
            const int mt = mS[t];
            cnt += mt;
            if (t >= 1 && mt) {
                const int cur = tagS[t];
                const int prv = tagS[t - 1];
                sc += lgb[t * NCLS + cur] + trS[prv * NCLS + cur];
            }
        }
#pragma unroll
        for (int off = 16; off; off >>= 1) {
            sc  += __shfl_xor_sync(0xffffffffu, sc,  off);
            cnt += __shfl_xor_sync(0xffffffffu, cnt, off);
        }
        if (lane == 0) {
            const int first = tagS[0];
            sc += stS[first] + lgb[first];
            sc += enS[tagS[cnt - 1]];
            num_sh = sc;
        }
    }

    __syncthreads();

    // ---- Phase D: publish llh; last finished block reduces ----
    if (tid == 0) {
        g_llh[b] = num_sh - den_sh;
        __threadfence();
        const int old = atomicAdd(&g_done, 1);
        isLast = (old == BATCH - 1) ? 1 : 0;
    }
    __syncthreads();

    if (isLast) {
        if (tid < 128) {
            float v = g_llh[tid];
#pragma unroll
            for (int off = 16; off; off >>= 1)
                v += __shfl_xor_sync(0xffffffffu, v, off);
            if (lane == 0) wsum[warp] = v;
        }
        __syncthreads();
        if (tid == 0) {
            const float tot = (wsum[0] + wsum[1]) + (wsum[2] + wsum[3]);
            out[0] = -tot / (float)BATCH;
            g_done = 0;   // reset for next graph replay
        }
    }
}

extern "C" void kernel_launch(void* const* d_in, const int* in_sizes, int n_in,
                              void* d_out, int out_size)
{
    const float* feat   = (const float*)d_in[0];
    const int*   labels = (const int*)d_in[1];
    const int*   mask   = (const int*)d_in[2];
    const float* W      = (const float*)d_in[3];
    const float* bias   = (const float*)d_in[4];
    const float* st     = (const float*)d_in[5];
    const float* en     = (const float*)d_in[6];
    const float* tr     = (const float*)d_in[7];

    float* out = (float*)d_out;

    cudaFuncSetAttribute(fused_kernel,
                         cudaFuncAttributeMaxDynamicSharedMemorySize, SMEM_TOTAL);
    fused_kernel<<<BATCH, 512, SMEM_TOTAL>>>(feat, labels, mask, W, bias,
                                             st, en, tr, out);
}